// round 16
// baseline (speedup 1.0000x reference)
#include <cuda_runtime.h>

// Problem constants
#define B_TOTAL  2
#define C_IN     32
#define WDIM     64
#define J_TOTAL  4096
#define S_TOTAL  256
#define HID      64
#define C_OUT    32
#define NMON     45      // monomials x^i y^j, i+j<=8

// g_M[b][h][45]: sum_s gelu(a_jh + q_bsh) ~= sum_m M_m x^i(m) y^j(m)
__device__ float g_M[B_TOTAL * HID * NMON];

// monomial enumeration: i outer 0..8, j inner 0..8-i  (offset walk in eval matches)
__device__ const signed char MON_I[NMON] = {
    0,0,0,0,0,0,0,0,0, 1,1,1,1,1,1,1,1, 2,2,2,2,2,2,2, 3,3,3,3,3,3,
    4,4,4,4,4, 5,5,5,5, 6,6,6, 7,7, 8};
__device__ const signed char MON_J[NMON] = {
    0,1,2,3,4,5,6,7,8, 0,1,2,3,4,5,6,7, 0,1,2,3,4,5,6, 0,1,2,3,4,5,
    0,1,2,3,4, 0,1,2,3, 0,1,2, 0,1, 0};
__device__ const float FACT[9] = {1.f,1.f,2.f,6.f,24.f,120.f,720.f,5040.f,40320.f};

// Phi(t) via Abramowitz-Stegun 7.1.26 (abs err ~1.5e-7)
__device__ __forceinline__ float Phi_f(float t) {
    float u  = t * 0.70710678118654752f;
    float au = fabsf(u);
    float k  = __fdividef(1.0f, fmaf(0.3275911f, au, 1.0f));
    float p  = fmaf(fmaf(fmaf(fmaf(1.061405429f, k, -1.453152027f),
                              k,  1.421413741f),
                         k, -0.284496736f),
                    k,  0.254829592f) * k;
    float e  = __expf(-u * u);
    float pe = p * e;
    float w  = (u >= 0.0f) ? (2.0f - pe) : pe;
    return 0.5f * w;
}

__device__ __forceinline__ float powi_f(float x, int n) {
    float r = 1.0f;
    for (int k = 0; k < n; k++) r *= x;
    return r;
}

// ---------- kernel 1: Taylor coefficients + monomial re-expansion ----------
__global__ __launch_bounds__(256)
void coeff_kernel(const float* __restrict__ v,
                  const int* __restrict__ indices,
                  const float* __restrict__ W1,
                  const float* __restrict__ b1) {
    __shared__ float red[8][9];
    __shared__ float csum[9];
    int s = threadIdx.x;            // 0..255 == S_TOTAL
    int h = blockIdx.x;
    int b = blockIdx.y;

    float w1x = W1[h];
    float w1y = W1[HID + h];
    float a0  = 0.5f * (w1x + w1y);

    int idx = indices[s] & (J_TOTAL - 1);
    int ix  = idx & (WDIM - 1);
    int iy  = idx >> 6;
    float q = b1[h] - (ix * (1.0f / 63.0f)) * w1x - (iy * (1.0f / 63.0f)) * w1y;
    const float* vb = v + (size_t)b * C_IN * J_TOTAL + idx;
#pragma unroll
    for (int c = 0; c < C_IN; c++)
        q = fmaf(vb[(size_t)c * J_TOTAL], W1[(2 + c) * HID + h], q);

    float t  = a0 + q;
    float t2 = t * t;
    float t4 = t2 * t2;
    float t6 = t4 * t2;
    float ph = 0.3989422804014327f * __expf(-0.5f * t2);  // phi(t)
    float PH = Phi_f(t);                                  // Phi(t)

    // c_k = gelu^(k)(t)/k!,  gelu(x)=x*Phi(x), phi' = -x phi
    float c[9];
    c[0] = t * PH;
    c[1] = fmaf(t, ph, PH);
    c[2] = (2.0f - t2) * ph * 0.5f;
    c[3] = (t2 - 4.0f) * t * ph * (1.0f / 6.0f);
    c[4] = (-t4 + 7.0f * t2 - 4.0f) * ph * (1.0f / 24.0f);
    c[5] = (t4 - 11.0f * t2 + 18.0f) * t * ph * (1.0f / 120.0f);
    c[6] = (-t6 + 16.0f * t4 - 51.0f * t2 + 18.0f) * ph * (1.0f / 720.0f);
    c[7] = (t6 - 22.0f * t4 + 115.0f * t2 - 120.0f) * t * ph * (1.0f / 5040.0f);
    c[8] = (-t6 * t2 + 29.0f * t6 - 225.0f * t4 + 465.0f * t2 - 120.0f) * ph * (1.0f / 40320.0f);

#pragma unroll
    for (int k = 0; k < 9; k++) {
        float x = c[k];
#pragma unroll
        for (int o = 16; o; o >>= 1)
            x += __shfl_xor_sync(0xffffffff, x, o);
        c[k] = x;
    }
    int lane = s & 31, w = s >> 5;
    if (lane == 0)
#pragma unroll
        for (int k = 0; k < 9; k++) red[w][k] = c[k];
    __syncthreads();

    if (s < 9) {
        float acc = 0.0f;
#pragma unroll
        for (int w2 = 0; w2 < 8; w2++) acc += red[w2][s];
        csum[s] = acc;
    }
    __syncthreads();

    // Monomial re-expansion: G(d) = sum_k csum[k] d^k, d = wx x + wy y - a0.
    // coeff of x^i y^j = sum_{k>=i+j} csum[k] * k!/(i! j! l!) * wx^i wy^j (-a0)^l, l=k-i-j
    if (s < NMON) {
        int i = MON_I[s], j = MON_J[s];
        float na0  = -a0;
        float base = powi_f(w1x, i) * powi_f(w1y, j);
        float inv_ij = 1.0f / (FACT[i] * FACT[j]);
        float m = 0.0f, pna = 1.0f;
        for (int k = i + j; k <= 8; k++) {
            int l = k - i - j;
            m   = fmaf(csum[k], FACT[k] * inv_ij / FACT[l] * pna, m);
            pna *= na0;
        }
        g_M[(b * HID + h) * NMON + s] = m * base;
    }
}

// ---------- kernel 2: row-wise polynomial evaluation ----------
// block = (iy, b): y constant per block.
// R[h][i] = sum_j M[h][i][j] y^j ;  E[c][i] = sum_h W2[h][c] R[h][i] ;
// out[b,c,iy*64+ix] = Horner_x(E[c]) / S + b2[c]
__global__ __launch_bounds__(256)
void eval_kernel(const float* __restrict__ W2,
                 const float* __restrict__ b2,
                 float* __restrict__ out) {
    __shared__ float Ms[HID * NMON];   // 11.25 KB
    __shared__ float W2s[HID * C_OUT]; // 8 KB
    __shared__ float Rs[HID * 9];      // 2.25 KB
    __shared__ float Es[C_OUT * 9];    // 1.125 KB
    __shared__ float b2s[C_OUT];

    int tid = threadIdx.x;
    int iy  = blockIdx.x;
    int b   = blockIdx.y;

    for (int i = tid; i < HID * NMON; i += 256) Ms[i] = g_M[b * HID * NMON + i];
    for (int i = tid; i < HID * C_OUT; i += 256) W2s[i] = W2[i];
    if (tid < C_OUT) b2s[tid] = b2[tid];
    __syncthreads();

    float y = iy * (1.0f / 63.0f);

    // Phase 1: collapse y (64 threads, one per h)
    if (tid < HID) {
        int base = tid * NMON, o = 0;
#pragma unroll
        for (int i = 0; i < 9; i++) {
            int deg = 8 - i;
            float p = Ms[base + o + deg];
            for (int jj = deg - 1; jj >= 0; jj--)
                p = fmaf(p, y, Ms[base + o + jj]);
            Rs[tid * 9 + i] = p;
            o += deg + 1;
        }
    }
    __syncthreads();

    // Phase 2: E[c][i] = sum_h W2[h][c] * R[h][i]  (288 entries)
    for (int e = tid; e < C_OUT * 9; e += 256) {
        int c = e / 9, i = e - c * 9;
        float sum = 0.0f;
#pragma unroll 8
        for (int hh = 0; hh < HID; hh++)
            sum = fmaf(W2s[hh * C_OUT + c], Rs[hh * 9 + i], sum);
        Es[e] = sum;
    }
    __syncthreads();

    // Phase 3: 2048 outputs (32 c x 64 ix), 8 per thread; x fixed per thread.
    int ix = tid & 63;
    float x = ix * (1.0f / 63.0f);
#pragma unroll
    for (int r = 0; r < 8; r++) {
        int o = tid + r * 256;
        int c = o >> 6;                      // warp-uniform
        float p = Es[c * 9 + 8];
#pragma unroll
        for (int i = 7; i >= 0; i--)
            p = fmaf(p, x, Es[c * 9 + i]);
        out[((size_t)b * C_OUT + c) * J_TOTAL + iy * WDIM + ix] =
            fmaf(p, 1.0f / (float)S_TOTAL, b2s[c]);
    }
}

extern "C" void kernel_launch(void* const* d_in, const int* in_sizes, int n_in,
                              void* d_out, int out_size) {
    const float* v       = (const float*)d_in[0];
    const int*   indices = (const int*)d_in[1];
    const float* W1      = (const float*)d_in[2];
    const float* b1      = (const float*)d_in[3];
    const float* W2      = (const float*)d_in[4];
    const float* b2      = (const float*)d_in[5];
    float*       out     = (float*)d_out;

    coeff_kernel<<<dim3(HID, B_TOTAL), S_TOTAL>>>(v, indices, W1, b1);
    eval_kernel<<<dim3(WDIM, B_TOTAL), 256>>>(W2, b2, out);
}